// round 2
// baseline (speedup 1.0000x reference)
#include <cuda_runtime.h>

#define Vn 55
#define Cn 64
#define Dn 64
#define Tn 128
#define Nn 64
#define NTn (Nn * Tn)          // 8192
#define VD (Vn * Dn)           // 3520
#define VC (Vn * Cn)           // 3520
#define TOTAL (NTn * VD)       // 28,835,840

// Intermediate g in [n][t][d][v] layout (temporal kernel reads contiguous v)
__device__ float g_buf[TOTAL];
// Precomputed fused parameters
__device__ float d_mT[Cn * 56];   // transposed mask: d_mT[c*56+u] = tanh(fm[u*C+c])+1
__device__ float d_A1[VD];        // BN1 scale, [u*D+d]
__device__ float d_B1[VD];        // BN1 shift with conv bias folded
__device__ float d_A2[Dn];        // BN2 scale
__device__ float d_B2[Dn];        // BN2 shift

typedef unsigned long long u64t;

__device__ __forceinline__ u64t pack_dup(float v) {
    u64t r; unsigned ui = __float_as_uint(v);
    asm("mov.b64 %0, {%1, %1};" : "=l"(r) : "r"(ui));
    return r;
}
__device__ __forceinline__ u64t pack2(float lo, float hi) {
    u64t r;
    asm("mov.b64 %0, {%1, %2};" : "=l"(r) : "r"(__float_as_uint(lo)), "r"(__float_as_uint(hi)));
    return r;
}
__device__ __forceinline__ void fma2(u64t& acc, u64t a, u64t b) {
    asm("fma.rn.f32x2 %0, %1, %2, %0;" : "+l"(acc) : "l"(a), "l"(b));
}
__device__ __forceinline__ void unpack2(u64t v, float& lo, float& hi) {
    asm("mov.b64 {%0, %1}, %2;" : "=f"(lo), "=f"(hi) : "l"(v));
}

__global__ __launch_bounds__(256) void prep_kernel(
    const float* __restrict__ fm, const float* __restrict__ b,
    const float* __restrict__ g1, const float* __restrict__ be1,
    const float* __restrict__ m1, const float* __restrict__ v1,
    const float* __restrict__ g2, const float* __restrict__ be2,
    const float* __restrict__ m2, const float* __restrict__ v2)
{
    int i = blockIdx.x * 256 + threadIdx.x;
    if (i < VC) {
        int u = i >> 6;          // i / 64
        int c = i & 63;
        d_mT[c * 56 + u] = tanhf(fm[i]) + 1.0f;
    }
    if (i < VD) {
        float a = g1[i] * rsqrtf(v1[i] + 1e-5f);
        d_A1[i] = a;
        d_B1[i] = be1[i] + a * (b[i & 63] - m1[i]);
    }
    if (i < Dn) {
        float a = g2[i] * rsqrtf(v2[i] + 1e-5f);
        d_A2[i] = a;
        d_B2[i] = be2[i] - a * m2[i];
    }
}

// One block per 4 consecutive time steps of one n.
// Spatial shift + mask + 55x64x64 GEMM (x4 t) + BN1 + inverse shift + ReLU.
__global__ __launch_bounds__(256) void kernelA(const float* __restrict__ x,
                                               const float* __restrict__ W)
{
    __shared__ __align__(16) float ws[Cn * Dn];         // W row-major (16 KB)
    __shared__ __align__(16) float hsT[4 * Cn * 56];    // hsT[tl][c][u], 56-pad (56 KB)
    // hsT region is reused as output staging after the GEMM.

    const int tid = threadIdx.x;
    const int bid = blockIdx.x;
    const int n  = bid >> 5;           // 32 blocks per n
    const int t0 = (bid & 31) << 2;    // 4 t per block

    // Load W
    for (int i = tid; i < Cn * Dn; i += 256) ws[i] = W[i];

    // Build hsT[tl][c][u] = x[n, c, t0+tl, (u+c)%55] * mT[c][u]   (u=55 pad -> 0)
    const float* xn = x + (size_t)n * Cn * Tn * Vn + t0 * Vn;
    for (int tl = 0; tl < 4; tl++) {
        const float* xt = xn + tl * Vn;
        float* hs = &hsT[tl * (Cn * 56)];
        for (int i = tid; i < Cn * 56; i += 256) {
            int c = i / 56;
            int u = i - c * 56;
            float val = 0.0f;
            if (u < Vn) {
                int s = u + c;
                if (s >= Vn) s -= Vn;
                if (s >= Vn) s -= Vn;
                val = xt[(size_t)c * (Tn * Vn) + s] * d_mT[i];
            }
            hs[i] = val;
        }
    }
    __syncthreads();

    // GEMM: y[tl][u][d] = sum_c hsT[tl][c][u] * ws[c][d]
    // 224 active threads: dt in [0,8) (8 d's), ut in [0,7) (8 u's), tl in [0,4)
    const int dt  = tid & 7;
    const int tmp = tid >> 3;
    const int ut  = tmp % 7;
    const int tl  = tmp / 7;
    const bool active = (tid < 224);

    u64t acc[8][4];
#pragma unroll
    for (int a = 0; a < 8; a++)
#pragma unroll
        for (int j = 0; j < 4; j++) acc[a][j] = 0ull;

    if (active) {
        const float* hs = &hsT[tl * (Cn * 56) + ut * 8];
        const float* wp = &ws[dt * 8];
#pragma unroll 4
        for (int c = 0; c < Cn; c++) {
            float4 wa = *reinterpret_cast<const float4*>(wp + c * Dn);
            float4 wb = *reinterpret_cast<const float4*>(wp + c * Dn + 4);
            u64t w0 = pack2(wa.x, wa.y), w1 = pack2(wa.z, wa.w);
            u64t w2 = pack2(wb.x, wb.y), w3 = pack2(wb.z, wb.w);
            float4 ha = *reinterpret_cast<const float4*>(hs + c * 56);
            float4 hb = *reinterpret_cast<const float4*>(hs + c * 56 + 4);
            u64t h;
            h = pack_dup(ha.x); fma2(acc[0][0], h, w0); fma2(acc[0][1], h, w1); fma2(acc[0][2], h, w2); fma2(acc[0][3], h, w3);
            h = pack_dup(ha.y); fma2(acc[1][0], h, w0); fma2(acc[1][1], h, w1); fma2(acc[1][2], h, w2); fma2(acc[1][3], h, w3);
            h = pack_dup(ha.z); fma2(acc[2][0], h, w0); fma2(acc[2][1], h, w1); fma2(acc[2][2], h, w2); fma2(acc[2][3], h, w3);
            h = pack_dup(ha.w); fma2(acc[3][0], h, w0); fma2(acc[3][1], h, w1); fma2(acc[3][2], h, w2); fma2(acc[3][3], h, w3);
            h = pack_dup(hb.x); fma2(acc[4][0], h, w0); fma2(acc[4][1], h, w1); fma2(acc[4][2], h, w2); fma2(acc[4][3], h, w3);
            h = pack_dup(hb.y); fma2(acc[5][0], h, w0); fma2(acc[5][1], h, w1); fma2(acc[5][2], h, w2); fma2(acc[5][3], h, w3);
            h = pack_dup(hb.z); fma2(acc[6][0], h, w0); fma2(acc[6][1], h, w1); fma2(acc[6][2], h, w2); fma2(acc[6][3], h, w3);
            h = pack_dup(hb.w); fma2(acc[7][0], h, w0); fma2(acc[7][1], h, w1); fma2(acc[7][2], h, w2); fma2(acc[7][3], h, w3);
        }
    }
    __syncthreads();   // all GEMM reads of hsT complete

    // Epilogue: BN1 + ReLU + inverse shift scatter into staging (reuse hsT area)
    // out_s[tl][d*55 + (u+d)%55]
    if (active) {
        float* out_s = &hsT[tl * (Cn * 56)];
#pragma unroll
        for (int uu = 0; uu < 8; uu++) {
            int u = ut * 8 + uu;
            if (u < Vn) {
#pragma unroll
                for (int j = 0; j < 4; j++) {
                    float lo, hi;
                    unpack2(acc[uu][j], lo, hi);
                    int d0 = dt * 8 + j * 2;
                    int idx0 = u * Dn + d0;
                    float y0 = fmaxf(d_A1[idx0] * lo + d_B1[idx0], 0.0f);
                    float y1 = fmaxf(d_A1[idx0 + 1] * hi + d_B1[idx0 + 1], 0.0f);
                    int v0 = u + d0;
                    if (v0 >= Vn) v0 -= Vn;
                    if (v0 >= Vn) v0 -= Vn;
                    int v1 = v0 + 1;
                    if (v1 >= Vn) v1 -= Vn;
                    out_s[d0 * Vn + v0] = y0;
                    out_s[(d0 + 1) * Vn + v1] = y1;
                }
            }
        }
    }
    __syncthreads();

    // Coalesced store of g[n][t][d][v]
    float* gout = &g_buf[((size_t)(n * Tn + t0)) * VD];
#pragma unroll
    for (int tl2 = 0; tl2 < 4; tl2++) {
        const float* src = &hsT[tl2 * (Cn * 56)];
        float* dst = gout + tl2 * VD;
        for (int j = tid; j < VD; j += 256) dst[j] = src[j];
    }
}

// Elementwise: temporal shift + BN2 + residual + ReLU. Fully coalesced.
__global__ __launch_bounds__(256) void kernelB(const float* __restrict__ x,
                                               float* __restrict__ out)
{
    int idx = blockIdx.x * 256 + threadIdx.x;   // < 28,835,840
    int v = idx % Vn;
    int r = idx / Vn;       // (n*64+c)*128 + t
    int t = r & 127;
    int nc = r >> 7;        // n*64+c
    int c = nc & 63;
    int off = (c % 3) - 1;
    int tt = t + off;
    float gval = 0.0f;
    if ((unsigned)tt < (unsigned)Tn) {
        int n = nc >> 6;
        gval = g_buf[((size_t)(n * Tn + tt)) * VD + c * Vn + v];
    }
    float res = d_A2[c] * gval + d_B2[c] + x[idx];
    out[idx] = fmaxf(res, 0.0f);
}

extern "C" void kernel_launch(void* const* d_in, const int* in_sizes, int n_in,
                              void* d_out, int out_size)
{
    const float* x   = (const float*)d_in[0];
    const float* W   = (const float*)d_in[1];
    const float* b   = (const float*)d_in[2];
    const float* fm  = (const float*)d_in[3];
    const float* g1  = (const float*)d_in[4];
    const float* be1 = (const float*)d_in[5];
    const float* m1  = (const float*)d_in[6];
    const float* v1  = (const float*)d_in[7];
    const float* g2  = (const float*)d_in[8];
    const float* be2 = (const float*)d_in[9];
    const float* m2  = (const float*)d_in[10];
    const float* v2  = (const float*)d_in[11];
    float* out = (float*)d_out;

    prep_kernel<<<14, 256>>>(fm, b, g1, be1, m1, v1, g2, be2, m2, v2);
    kernelA<<<NTn / 4, 256>>>(x, W);
    kernelB<<<TOTAL / 256, 256>>>(x, out);
}